// round 11
// baseline (speedup 1.0000x reference)
#include <cuda_runtime.h>
#include <cstdint>

// Distral multi-head tiny MLP (N = 32769 heads). R9 established: L2 persists
// across graph replays; evict_last on W1+b1 (52MB) + evict_first on W2 gives
// 16.9us (DRAM no longer saturated in steady state -> latency-exposed).
// R11: same policy split, but each warp processes TWO consecutive heads per
// iteration with all 18 LDG.128 batched before compute (doubles in-flight
// bytes per warp). No smem, no barriers.

#define HID 100
#define OUT 5

__device__ __forceinline__ uint64_t pol_keep() {
    uint64_t p;
    asm("createpolicy.fractional.L2::evict_last.b64 %0, 1.0;" : "=l"(p));
    return p;
}
__device__ __forceinline__ uint64_t pol_stream() {
    uint64_t p;
    asm("createpolicy.fractional.L2::evict_first.b64 %0, 1.0;" : "=l"(p));
    return p;
}
__device__ __forceinline__ float4 ldg_hint(const float4* p, uint64_t pol) {
    float4 v;
    asm volatile("ld.global.nc.L2::cache_hint.v4.f32 {%0,%1,%2,%3}, [%4], %5;"
                 : "=f"(v.x), "=f"(v.y), "=f"(v.z), "=f"(v.w)
                 : "l"(p), "l"(pol));
    return v;
}

struct Head {
    float4 w1[3], b1v, w2[OUT];
    float  x0, x1, x2;
    float  bo[OUT];
};

__device__ __forceinline__ void load_head(
    Head& s, int head, int lane, uint64_t pk, uint64_t ps,
    const float* __restrict__ W1, const float* __restrict__ b1,
    const float* __restrict__ W2, const float* __restrict__ x,
    const float* __restrict__ b2)
{
    const float4* g1 = (const float4*)(W1 + (size_t)head * (HID * 3));
    const float4* gb = (const float4*)(b1 + (size_t)head * HID);
    const float4* g2 = (const float4*)(W2 + (size_t)head * (OUT * HID));
    if (lane < 25) {
        s.w1[0] = ldg_hint(g1 + 3 * lane + 0, pk);
        s.w1[1] = ldg_hint(g1 + 3 * lane + 1, pk);
        s.w1[2] = ldg_hint(g1 + 3 * lane + 2, pk);
        s.b1v   = ldg_hint(gb + lane, pk);
        #pragma unroll
        for (int o = 0; o < OUT; o++) s.w2[o] = ldg_hint(g2 + 25 * o + lane, ps);
    } else {
        s.w1[0] = s.w1[1] = s.w1[2] = s.b1v = make_float4(0.f, 0.f, 0.f, 0.f);
        #pragma unroll
        for (int o = 0; o < OUT; o++) s.w2[o] = make_float4(0.f, 0.f, 0.f, 0.f);
    }
    s.x0 = __ldg(x + (size_t)head * 3 + 0);
    s.x1 = __ldg(x + (size_t)head * 3 + 1);
    s.x2 = __ldg(x + (size_t)head * 3 + 2);
    #pragma unroll
    for (int o = 0; o < OUT; o++) s.bo[o] = __ldg(b2 + (size_t)head * OUT + o);
}

__device__ __forceinline__ void compute_head(
    const Head& s, int head, int lane, float* __restrict__ out)
{
    const float f[12] = { s.w1[0].x, s.w1[0].y, s.w1[0].z, s.w1[0].w,
                          s.w1[1].x, s.w1[1].y, s.w1[1].z, s.w1[1].w,
                          s.w1[2].x, s.w1[2].y, s.w1[2].z, s.w1[2].w };
    const float bb[4] = { s.b1v.x, s.b1v.y, s.b1v.z, s.b1v.w };

    float h[4];
    #pragma unroll
    for (int k = 0; k < 4; k++) {
        float v = fmaf(f[3 * k + 0], s.x0,
                  fmaf(f[3 * k + 1], s.x1,
                  fmaf(f[3 * k + 2], s.x2, bb[k])));
        h[k] = fmaxf(v, 0.0f);
    }

    float logits[OUT];
    #pragma unroll
    for (int o = 0; o < OUT; o++) {
        float4 q = s.w2[o];
        float p = fmaf(q.x, h[0], fmaf(q.y, h[1], fmaf(q.z, h[2], q.w * h[3])));
        #pragma unroll
        for (int sft = 16; sft; sft >>= 1)
            p += __shfl_xor_sync(0xffffffffu, p, sft);
        logits[o] = p + s.bo[o];
    }

    float mx = logits[0];
    #pragma unroll
    for (int o = 1; o < OUT; o++) mx = fmaxf(mx, logits[o]);
    float e[OUT], sum = 0.0f;
    #pragma unroll
    for (int o = 0; o < OUT; o++) { e[o] = __expf(logits[o] - mx); sum += e[o]; }
    float inv = __frcp_rn(sum);

    if (lane < OUT)
        out[(size_t)head * OUT + lane] = e[lane] * inv;
}

__global__ __launch_bounds__(256) void distral_kernel(
    const float* __restrict__ x,
    const float* __restrict__ W1,
    const float* __restrict__ b1,
    const float* __restrict__ W2,
    const float* __restrict__ b2,
    float* __restrict__ out,
    int n_heads)
{
    const int lane  = threadIdx.x & 31;
    const int gwarp = (blockIdx.x * blockDim.x + threadIdx.x) >> 5;
    const int nwarp = (gridDim.x * blockDim.x) >> 5;

    const uint64_t pk = pol_keep();    // W1,b1 resident (52.4MB of 126MB L2)
    const uint64_t ps = pol_stream();  // W2 streaming

    const int n_pairs = (n_heads + 1) >> 1;

    for (int pr = gwarp; pr < n_pairs; pr += nwarp) {
        const int h0 = pr * 2;
        const int h1 = h0 + 1;
        const bool has1 = (h1 < n_heads);

        Head s0, s1;
        load_head(s0, h0, lane, pk, ps, W1, b1, W2, x, b2);
        if (has1) load_head(s1, h1, lane, pk, ps, W1, b1, W2, x, b2);

        compute_head(s0, h0, lane, out);
        if (has1) compute_head(s1, h1, lane, out);
    }
}

extern "C" void kernel_launch(void* const* d_in, const int* in_sizes, int n_in,
                              void* d_out, int out_size)
{
    const float* x  = (const float*)d_in[0];
    const float* W1 = (const float*)d_in[1];
    const float* b1 = (const float*)d_in[2];
    const float* W2 = (const float*)d_in[3];
    const float* b2 = (const float*)d_in[4];
    float* out = (float*)d_out;

    const int n_heads = in_sizes[0] / 3;   // x is (N, 3)

    const int blocks = 148 * 4;            // 4736 warps, ~3.5 pairs each
    distral_kernel<<<blocks, 256>>>(x, W1, b1, W2, b2, out, n_heads);
}

// round 12
// speedup vs baseline: 1.2388x; 1.2388x over previous
#include <cuda_runtime.h>
#include <cstdint>

// Distral multi-head tiny MLP (N = 32769 heads). Established: L2 persists
// across graph replays; evict_last W1+b1 (52MB) + evict_first W2 = 16.9us,
// steady-state DRAM ~68MB no longer saturated (latency-exposed), occupancy
// (70% @ 40 regs) is the winning regime. R12: identical kernel, but W2 gets
// fractional protection 0.35 (protected total ~75MB = 60% of L2, below the
// thrash point R10 hit at 91MB). Steady-state DRAM -> ~45MB.

#define HID 100
#define OUT 5

__device__ __forceinline__ uint64_t pol_keep() {
    uint64_t p;
    asm("createpolicy.fractional.L2::evict_last.b64 %0, 1.0;" : "=l"(p));
    return p;
}
__device__ __forceinline__ uint64_t pol_w2() {
    uint64_t p;
    // 35% of W2 lines evict_last (resident), 65% evict_first (streaming)
    asm("createpolicy.fractional.L2::evict_last.L2::evict_first.b64 %0, 0.35;"
        : "=l"(p));
    return p;
}
__device__ __forceinline__ float4 ldg_hint(const float4* p, uint64_t pol) {
    float4 v;
    asm volatile("ld.global.nc.L2::cache_hint.v4.f32 {%0,%1,%2,%3}, [%4], %5;"
                 : "=f"(v.x), "=f"(v.y), "=f"(v.z), "=f"(v.w)
                 : "l"(p), "l"(pol));
    return v;
}

__global__ __launch_bounds__(256, 6) void distral_kernel(
    const float* __restrict__ x,
    const float* __restrict__ W1,
    const float* __restrict__ b1,
    const float* __restrict__ W2,
    const float* __restrict__ b2,
    float* __restrict__ out,
    int n_heads)
{
    const int lane  = threadIdx.x & 31;
    const int gwarp = (blockIdx.x * blockDim.x + threadIdx.x) >> 5;
    const int nwarp = (gridDim.x * blockDim.x) >> 5;

    const uint64_t pk = pol_keep();  // W1,b1: fully resident (52.4MB)
    const uint64_t pw = pol_w2();    // W2: 35% resident / 65% streaming

    // lane l (l<25) owns hidden units j in [4l, 4l+4)
    for (int head = gwarp; head < n_heads; head += nwarp) {
        const float4* g1 = (const float4*)(W1 + (size_t)head * (HID * 3));
        const float4* gb = (const float4*)(b1 + (size_t)head * HID);
        const float4* g2 = (const float4*)(W2 + (size_t)head * (OUT * HID));

        float4 w1a, w1b, w1c, b1v, w2v[OUT];
        if (lane < 25) {
            w1a = ldg_hint(g1 + 3 * lane + 0, pk);
            w1b = ldg_hint(g1 + 3 * lane + 1, pk);
            w1c = ldg_hint(g1 + 3 * lane + 2, pk);
            b1v = ldg_hint(gb + lane, pk);
            #pragma unroll
            for (int o = 0; o < OUT; o++) w2v[o] = ldg_hint(g2 + 25 * o + lane, pw);
        } else {
            w1a = w1b = w1c = b1v = make_float4(0.f, 0.f, 0.f, 0.f);
            #pragma unroll
            for (int o = 0; o < OUT; o++) w2v[o] = make_float4(0.f, 0.f, 0.f, 0.f);
        }

        const float x0 = __ldg(x + (size_t)head * 3 + 0);
        const float x1 = __ldg(x + (size_t)head * 3 + 1);
        const float x2 = __ldg(x + (size_t)head * 3 + 2);

        const float f[12] = { w1a.x, w1a.y, w1a.z, w1a.w,
                              w1b.x, w1b.y, w1b.z, w1b.w,
                              w1c.x, w1c.y, w1c.z, w1c.w };
        const float bb[4] = { b1v.x, b1v.y, b1v.z, b1v.w };

        float h[4];
        #pragma unroll
        for (int k = 0; k < 4; k++) {
            float v = fmaf(f[3 * k + 0], x0,
                      fmaf(f[3 * k + 1], x1,
                      fmaf(f[3 * k + 2], x2, bb[k])));
            h[k] = fmaxf(v, 0.0f);
        }

        float logits[OUT];
        #pragma unroll
        for (int o = 0; o < OUT; o++) {
            float4 q = w2v[o];
            float p = fmaf(q.x, h[0], fmaf(q.y, h[1], fmaf(q.z, h[2], q.w * h[3])));
            #pragma unroll
            for (int s = 16; s; s >>= 1)
                p += __shfl_xor_sync(0xffffffffu, p, s);
            logits[o] = p + __ldg(b2 + (size_t)head * OUT + o);
        }

        float mx = logits[0];
        #pragma unroll
        for (int o = 1; o < OUT; o++) mx = fmaxf(mx, logits[o]);
        float e[OUT], sum = 0.0f;
        #pragma unroll
        for (int o = 0; o < OUT; o++) { e[o] = __expf(logits[o] - mx); sum += e[o]; }
        float inv = __frcp_rn(sum);

        if (lane < OUT)
            out[(size_t)head * OUT + lane] = e[lane] * inv;
    }
}

extern "C" void kernel_launch(void* const* d_in, const int* in_sizes, int n_in,
                              void* d_out, int out_size)
{
    const float* x  = (const float*)d_in[0];
    const float* W1 = (const float*)d_in[1];
    const float* b1 = (const float*)d_in[2];
    const float* W2 = (const float*)d_in[3];
    const float* b2 = (const float*)d_in[4];
    float* out = (float*)d_out;

    const int n_heads = in_sizes[0] / 3;   // x is (N, 3)

    const int blocks = 148 * 6;            // fill the 6-blocks/SM residency
    distral_kernel<<<blocks, 256>>>(x, W1, b1, W2, b2, out, n_heads);
}